// round 1
// baseline (speedup 1.0000x reference)
#include <cuda_runtime.h>

#define NUM_USERS 50000
#define NUM_ITEMS 100000
#define NUM_NODES 150000   // NUM_USERS + NUM_ITEMS
#define LATENT_DIM 64
#define NNZ 4800000
#define BATCH 4096

// Scratch state (allocation-free, graph-capturable): ping-pong dense buffers,
// accumulator, and CSR row pointer built from the sorted edge_rows each launch.
__device__ float g_bufA[NUM_NODES * LATENT_DIM];
__device__ float g_bufB[NUM_NODES * LATENT_DIM];
__device__ float g_acc [NUM_NODES * LATENT_DIM];
__device__ int   g_row_ptr[NUM_NODES + 1];

// ---------------------------------------------------------------------------
// Init: concat(user_emb, item_emb) -> g_bufA (cur) and g_acc, in float4s.
// ---------------------------------------------------------------------------
__global__ void __launch_bounds__(256) init_kernel(const float4* __restrict__ user_emb,
                                                   const float4* __restrict__ item_emb)
{
    const int total  = NUM_NODES * LATENT_DIM / 4;   // 2.4M float4
    const int uquads = NUM_USERS * LATENT_DIM / 4;
    int i = blockIdx.x * blockDim.x + threadIdx.x;
    if (i >= total) return;
    float4 v = (i < uquads) ? __ldg(&user_emb[i]) : __ldg(&item_emb[i - uquads]);
    reinterpret_cast<float4*>(g_bufA)[i] = v;
    reinterpret_cast<float4*>(g_acc )[i] = v;
}

// ---------------------------------------------------------------------------
// Build CSR row_ptr from sorted edge_rows.
// row_ptr[r] = first edge index with rows[e] >= r.
// ---------------------------------------------------------------------------
__global__ void __launch_bounds__(256) rowptr_kernel(const int* __restrict__ rows)
{
    int e = blockIdx.x * blockDim.x + threadIdx.x;
    if (e >= NNZ) return;
    int r  = rows[e];
    int rp = (e == 0) ? -1 : rows[e - 1];
    for (int rr = rp + 1; rr <= r; ++rr) g_row_ptr[rr] = e;
    if (e == NNZ - 1) {
        for (int rr = r + 1; rr <= NUM_NODES; ++rr) g_row_ptr[rr] = NNZ;
    }
}

// ---------------------------------------------------------------------------
// SpMM: xout[r] = sum_{e in row r} vals[e] * xin[cols[e]];  g_acc[r] += xout[r]
// Warp per row. Two half-warps process two consecutive edges per iteration;
// each lane loads one float4 (row gather = 256B fully coalesced).
// flip selects the ping-pong direction (0: A->B, 1: B->A).
// ---------------------------------------------------------------------------
__global__ void __launch_bounds__(256) spmm_kernel(const int*   __restrict__ cols,
                                                   const float* __restrict__ vals,
                                                   int flip)
{
    const float4* __restrict__ xin  = reinterpret_cast<const float4*>(flip ? g_bufB : g_bufA);
    float4*       __restrict__ xout = reinterpret_cast<float4*>      (flip ? g_bufA : g_bufB);

    int warp = (blockIdx.x * blockDim.x + threadIdx.x) >> 5;
    int lane = threadIdx.x & 31;
    if (warp >= NUM_NODES) return;

    int start = g_row_ptr[warp];
    int end   = g_row_ptr[warp + 1];

    int sub = lane >> 4;      // which edge of the pair this half-warp handles
    int q   = lane & 15;      // float4 slot within the 64-float row

    float4 acc = make_float4(0.f, 0.f, 0.f, 0.f);

    #pragma unroll 4
    for (int e = start; e < end; e += 2) {
        int   ee = e + sub;
        bool  on = (ee < end);
        float v  = on ? __ldg(&vals[ee]) : 0.f;
        int   c  = on ? __ldg(&cols[ee]) : 0;
        float4 x = __ldg(&xin[(long long)c * 16 + q]);
        acc.x += v * x.x;
        acc.y += v * x.y;
        acc.z += v * x.z;
        acc.w += v * x.w;
    }

    // Merge the two half-warp partial sums (same q in both halves).
    acc.x += __shfl_xor_sync(0xffffffffu, acc.x, 16);
    acc.y += __shfl_xor_sync(0xffffffffu, acc.y, 16);
    acc.z += __shfl_xor_sync(0xffffffffu, acc.z, 16);
    acc.w += __shfl_xor_sync(0xffffffffu, acc.w, 16);

    long long o = (long long)warp * 16 + q;
    if (sub == 0) {
        // lanes 0-15: write the new layer embedding
        xout[o] = acc;
    } else {
        // lanes 16-31: fold into the running LightGCN accumulator
        float4 a = reinterpret_cast<float4*>(g_acc)[o];
        a.x += acc.x; a.y += acc.y; a.z += acc.z; a.w += acc.w;
        reinterpret_cast<float4*>(g_acc)[o] = a;
    }
}

// ---------------------------------------------------------------------------
// Final: gamma[b] = dot(acc[users[b]], acc[NUM_USERS+items[b]]) / 16
// (the two /(N_LAYERS+1)=/4 factors folded into a single 1/16).
// Warp per batch element.
// ---------------------------------------------------------------------------
__global__ void __launch_bounds__(256) dot_kernel(const int* __restrict__ users,
                                                  const int* __restrict__ items,
                                                  float* __restrict__ out)
{
    int warp = (blockIdx.x * blockDim.x + threadIdx.x) >> 5;
    int lane = threadIdx.x & 31;
    if (warp >= BATCH) return;

    long long u = users[warp];
    long long it = (long long)items[warp] + NUM_USERS;

    const float2* au = reinterpret_cast<const float2*>(g_acc + u  * LATENT_DIM);
    const float2* ai = reinterpret_cast<const float2*>(g_acc + it * LATENT_DIM);

    float2 a = au[lane];
    float2 b = ai[lane];
    float s = a.x * b.x + a.y * b.y;

    #pragma unroll
    for (int o = 16; o > 0; o >>= 1)
        s += __shfl_xor_sync(0xffffffffu, s, o);

    if (lane == 0) out[warp] = s * (1.0f / 16.0f);
}

// ---------------------------------------------------------------------------
extern "C" void kernel_launch(void* const* d_in, const int* in_sizes, int n_in,
                              void* d_out, int out_size)
{
    const float* user_emb  = (const float*)d_in[0];
    const float* item_emb  = (const float*)d_in[1];
    const int*   edge_rows = (const int*)  d_in[2];
    const int*   edge_cols = (const int*)  d_in[3];
    const float* edge_vals = (const float*)d_in[4];
    const int*   users     = (const int*)  d_in[5];
    const int*   items     = (const int*)  d_in[6];
    float*       out       = (float*)d_out;

    (void)in_sizes; (void)n_in; (void)out_size;

    // 1. init cur/acc with concatenated embeddings
    {
        int total = NUM_NODES * LATENT_DIM / 4;
        init_kernel<<<(total + 255) / 256, 256>>>(
            reinterpret_cast<const float4*>(user_emb),
            reinterpret_cast<const float4*>(item_emb));
    }

    // 2. build CSR row pointer from sorted edge_rows
    rowptr_kernel<<<(NNZ + 255) / 256, 256>>>(edge_rows);

    // 3. three propagation layers (ping-pong A->B->A->B), acc folded in-kernel
    {
        int blocks = (NUM_NODES * 32 + 255) / 256;   // warp per row
        spmm_kernel<<<blocks, 256>>>(edge_cols, edge_vals, 0);
        spmm_kernel<<<blocks, 256>>>(edge_cols, edge_vals, 1);
        spmm_kernel<<<blocks, 256>>>(edge_cols, edge_vals, 0);
    }

    // 4. batched dot products
    dot_kernel<<<(BATCH * 32 + 255) / 256, 256>>>(users, items, out);
}

// round 3
// speedup vs baseline: 1.0948x; 1.0948x over previous
#include <cuda_runtime.h>

#define NUM_USERS 50000
#define NUM_ITEMS 100000
#define NUM_NODES 150000   // NUM_USERS + NUM_ITEMS
#define LATENT_DIM 64
#define NNZ 4800000
#define BATCH 4096

// Scratch state (allocation-free, graph-capturable)
__device__ float g_bufA[NUM_NODES * LATENT_DIM];
__device__ float g_bufB[NUM_NODES * LATENT_DIM];
__device__ float g_acc [NUM_NODES * LATENT_DIM];
__device__ int   g_row_ptr[NUM_NODES + 1];

// ---------------------------------------------------------------------------
// Init: concat(user_emb, item_emb) -> g_bufA (cur) and g_acc, in float4s.
// ---------------------------------------------------------------------------
__global__ void __launch_bounds__(256) init_kernel(const float4* __restrict__ user_emb,
                                                   const float4* __restrict__ item_emb)
{
    const int total  = NUM_NODES * LATENT_DIM / 4;
    const int uquads = NUM_USERS * LATENT_DIM / 4;
    int i = blockIdx.x * blockDim.x + threadIdx.x;
    if (i >= total) return;
    float4 v = (i < uquads) ? __ldg(&user_emb[i]) : __ldg(&item_emb[i - uquads]);
    reinterpret_cast<float4*>(g_bufA)[i] = v;
    reinterpret_cast<float4*>(g_acc )[i] = v;
}

// ---------------------------------------------------------------------------
// Build CSR row_ptr from sorted edge_rows.
// ---------------------------------------------------------------------------
__global__ void __launch_bounds__(256) rowptr_kernel(const int* __restrict__ rows)
{
    int e = blockIdx.x * blockDim.x + threadIdx.x;
    if (e >= NNZ) return;
    int r  = rows[e];
    int rp = (e == 0) ? -1 : rows[e - 1];
    for (int rr = rp + 1; rr <= r; ++rr) g_row_ptr[rr] = e;
    if (e == NNZ - 1) {
        for (int rr = r + 1; rr <= NUM_NODES; ++rr) g_row_ptr[rr] = NNZ;
    }
}

// ---------------------------------------------------------------------------
// SpMM: warp per row. Edge metadata staged via one coalesced (col,val) load
// per lane per 32-edge chunk, distributed with shfl (ALL shfls executed by
// all lanes; out-of-range edges are neutralized by zeroing their val AFTER
// the shfl — covers both tail edges and the &31 wraparound). Inner loop does
// 4 edges/iteration: two half-warps x two gathers, two accumulators.
// ---------------------------------------------------------------------------
__global__ void __launch_bounds__(256) spmm_kernel(const int*   __restrict__ cols,
                                                   const float* __restrict__ vals,
                                                   int flip)
{
    const float4* __restrict__ xin  = reinterpret_cast<const float4*>(flip ? g_bufB : g_bufA);
    float4*       __restrict__ xout = reinterpret_cast<float4*>      (flip ? g_bufA : g_bufB);

    const unsigned FULL = 0xffffffffu;
    int warp = (blockIdx.x * blockDim.x + threadIdx.x) >> 5;
    int lane = threadIdx.x & 31;
    if (warp >= NUM_NODES) return;

    const int start = g_row_ptr[warp];
    const int end   = g_row_ptr[warp + 1];

    const int sub = lane >> 4;      // which edge of a pair this half-warp handles
    const int q   = lane & 15;      // float4 slot within the 64-float row

    const float4* __restrict__ xq = xin + q;   // lane-fixed column of the table

    float4 acc0 = make_float4(0.f, 0.f, 0.f, 0.f);
    float4 acc1 = make_float4(0.f, 0.f, 0.f, 0.f);

    for (int base = start; base < end; base += 32) {
        const int n = min(32, end - base);      // warp-uniform
        // coalesced metadata stage: one (col,val) per lane
        int   c = 0;
        float v = 0.f;
        if (lane < n) {
            c = __ldg(&cols[base + lane]);
            v = __ldg(&vals[base + lane]);
        }

        for (int j = 0; j < n; j += 4) {        // j, n warp-uniform -> converged
            const int e0 = j + sub;             // edges j, j+1
            const int e1 = j + 2 + sub;         // edges j+2, j+3

            // Unconditional shfls (all 32 lanes participate). Out-of-range
            // edges (e >= n, including any &31 wraparound since e<35 and
            // e>=32 implies e>=n) are killed by zeroing v afterwards.
            int   cc0 = __shfl_sync(FULL, c, e0 & 31);
            int   cc1 = __shfl_sync(FULL, c, e1 & 31);
            float vv0 = __shfl_sync(FULL, v, e0 & 31);
            float vv1 = __shfl_sync(FULL, v, e1 & 31);
            if (e0 >= n) vv0 = 0.f;
            if (e1 >= n) vv1 = 0.f;

            float4 x0 = __ldg(&xq[(size_t)cc0 * 16]);
            float4 x1 = __ldg(&xq[(size_t)cc1 * 16]);

            acc0.x += vv0 * x0.x;  acc0.y += vv0 * x0.y;
            acc0.z += vv0 * x0.z;  acc0.w += vv0 * x0.w;
            acc1.x += vv1 * x1.x;  acc1.y += vv1 * x1.y;
            acc1.z += vv1 * x1.z;  acc1.w += vv1 * x1.w;
        }
    }

    acc0.x += acc1.x; acc0.y += acc1.y; acc0.z += acc1.z; acc0.w += acc1.w;

    // merge the two half-warp partials (same q in both halves)
    acc0.x += __shfl_xor_sync(FULL, acc0.x, 16);
    acc0.y += __shfl_xor_sync(FULL, acc0.y, 16);
    acc0.z += __shfl_xor_sync(FULL, acc0.z, 16);
    acc0.w += __shfl_xor_sync(FULL, acc0.w, 16);

    const size_t o = (size_t)warp * 16 + q;
    if (sub == 0) {
        xout[o] = acc0;                       // lanes 0-15: new layer embedding
    } else {
        float4 a = reinterpret_cast<float4*>(g_acc)[o];   // lanes 16-31: acc += cur
        a.x += acc0.x; a.y += acc0.y; a.z += acc0.z; a.w += acc0.w;
        reinterpret_cast<float4*>(g_acc)[o] = a;
    }
}

// ---------------------------------------------------------------------------
// Final: gamma[b] = dot(acc[users[b]], acc[NUM_USERS+items[b]]) / 16
// ---------------------------------------------------------------------------
__global__ void __launch_bounds__(256) dot_kernel(const int* __restrict__ users,
                                                  const int* __restrict__ items,
                                                  float* __restrict__ out)
{
    int warp = (blockIdx.x * blockDim.x + threadIdx.x) >> 5;
    int lane = threadIdx.x & 31;
    if (warp >= BATCH) return;

    size_t u  = (size_t)users[warp];
    size_t it = (size_t)items[warp] + NUM_USERS;

    const float2* au = reinterpret_cast<const float2*>(g_acc + u  * LATENT_DIM);
    const float2* ai = reinterpret_cast<const float2*>(g_acc + it * LATENT_DIM);

    float2 a = au[lane];
    float2 b = ai[lane];
    float s = a.x * b.x + a.y * b.y;

    #pragma unroll
    for (int o = 16; o > 0; o >>= 1)
        s += __shfl_xor_sync(0xffffffffu, s, o);

    if (lane == 0) out[warp] = s * (1.0f / 16.0f);
}

// ---------------------------------------------------------------------------
extern "C" void kernel_launch(void* const* d_in, const int* in_sizes, int n_in,
                              void* d_out, int out_size)
{
    const float* user_emb  = (const float*)d_in[0];
    const float* item_emb  = (const float*)d_in[1];
    const int*   edge_rows = (const int*)  d_in[2];
    const int*   edge_cols = (const int*)  d_in[3];
    const float* edge_vals = (const float*)d_in[4];
    const int*   users     = (const int*)  d_in[5];
    const int*   items     = (const int*)  d_in[6];
    float*       out       = (float*)d_out;

    (void)in_sizes; (void)n_in; (void)out_size;

    {
        int total = NUM_NODES * LATENT_DIM / 4;
        init_kernel<<<(total + 255) / 256, 256>>>(
            reinterpret_cast<const float4*>(user_emb),
            reinterpret_cast<const float4*>(item_emb));
    }

    rowptr_kernel<<<(NNZ + 255) / 256, 256>>>(edge_rows);

    {
        int blocks = (NUM_NODES * 32 + 255) / 256;   // warp per row
        spmm_kernel<<<blocks, 256>>>(edge_cols, edge_vals, 0);
        spmm_kernel<<<blocks, 256>>>(edge_cols, edge_vals, 1);
        spmm_kernel<<<blocks, 256>>>(edge_cols, edge_vals, 0);
    }

    dot_kernel<<<(BATCH * 32 + 255) / 256, 256>>>(users, items, out);
}